// round 3
// baseline (speedup 1.0000x reference)
#include <cuda_runtime.h>
#include <mma.h>

using namespace nvcuda;

#define B_   32
#define CIN  96
#define HH   56
#define WW   56
#define HW   3136
#define P0   384
#define P1   72
#define EPS  1e-5f

// Scratch: expand output only (dw+project fused; g_h2 eliminated).
__device__ float g_h1[B_ * P0 * HW];

// ---------------------------------------------------------------------------
// Kernel 1: 1x1 expand (96 -> 384) + BN1 + ReLU6 via wmma tf32 -> g_h1.
// Per image GEMM: C[384 x 3136] = We[384 x 96] * X[96 x 3136]
// Block tile M=128 x N=64, full K=96. 8 warps as 4(M) x 2(N), warp 32x32.
// smem: As[128][100] + Bs[96][68] = 77,312 B (2 blocks/SM)
// grid = (49, 3, 32), block = 256
// ---------------------------------------------------------------------------
#define EA_LD 100
#define EB_LD 68
#define EC_LD 68

__global__ __launch_bounds__(256)
void expand_kernel(const float* __restrict__ x,
                   const float* __restrict__ we,
                   const float* __restrict__ g1, const float* __restrict__ b1,
                   const float* __restrict__ m1, const float* __restrict__ v1)
{
    extern __shared__ float sm[];
    float* As = sm;                    // [128][EA_LD]  (M x K)
    float* Bs = sm + 128 * EA_LD;      // [96][EB_LD]   (K x N)
    float* Cs = sm;                    // reuse for epilogue: [128][EC_LD]

    const int tid   = threadIdx.x;
    const int wid   = tid >> 5;
    const int lane  = tid & 31;
    const int nBase = blockIdx.x * 64;
    const int mBase = blockIdx.y * 128;
    const int b     = blockIdx.z;

    // --- Fill A: warp w -> rows [w*16, w*16+16), lane covers k in {l, l+32, l+64}
    #pragma unroll
    for (int i = 0; i < 16; i++) {
        int m = wid * 16 + i;
        const float* src = &we[(mBase + m) * CIN];
        float* dst = &As[m * EA_LD];
        #pragma unroll
        for (int kk = 0; kk < 3; kk++)
            dst[lane + 32 * kk] = wmma::__float_to_tf32(src[lane + 32 * kk]);
    }
    // --- Fill B: warp w -> k rows [w*12, w*12+12), lane covers p in {l, l+32}
    #pragma unroll
    for (int i = 0; i < 12; i++) {
        int k = wid * 12 + i;
        const float* src = &x[(b * CIN + k) * HW + nBase];
        float* dst = &Bs[k * EB_LD];
        dst[lane]      = wmma::__float_to_tf32(src[lane]);
        dst[lane + 32] = wmma::__float_to_tf32(src[lane + 32]);
    }
    __syncthreads();

    const int wm = (wid & 3) * 32;
    const int wn = (wid >> 2) * 32;

    wmma::fragment<wmma::accumulator, 16, 16, 8, float> acc[2][2];
    #pragma unroll
    for (int i = 0; i < 2; i++)
        #pragma unroll
        for (int j = 0; j < 2; j++) wmma::fill_fragment(acc[i][j], 0.f);

    #pragma unroll
    for (int k0 = 0; k0 < 96; k0 += 8) {
        wmma::fragment<wmma::matrix_a, 16, 16, 8, wmma::precision::tf32, wmma::row_major> af[2];
        wmma::fragment<wmma::matrix_b, 16, 16, 8, wmma::precision::tf32, wmma::row_major> bf[2];
        #pragma unroll
        for (int i = 0; i < 2; i++)
            wmma::load_matrix_sync(af[i], &As[(wm + i * 16) * EA_LD + k0], EA_LD);
        #pragma unroll
        for (int j = 0; j < 2; j++)
            wmma::load_matrix_sync(bf[j], &Bs[k0 * EB_LD + wn + j * 16], EB_LD);
        #pragma unroll
        for (int i = 0; i < 2; i++)
            #pragma unroll
            for (int j = 0; j < 2; j++)
                wmma::mma_sync(acc[i][j], af[i], bf[j], acc[i][j]);
    }

    __syncthreads();
    #pragma unroll
    for (int i = 0; i < 2; i++)
        #pragma unroll
        for (int j = 0; j < 2; j++)
            wmma::store_matrix_sync(&Cs[(wm + i * 16) * EC_LD + wn + j * 16],
                                    acc[i][j], EC_LD, wmma::mem_row_major);
    __syncthreads();

    // Epilogue: BN1 + ReLU6, float4 stores. 128 rows x 64 cols.
    #pragma unroll
    for (int it = 0; it < 8; it++) {
        int row = it * 16 + (tid >> 4);
        int col = (tid & 15) * 4;
        int o = mBase + row;
        float sc = g1[o] * rsqrtf(v1[o] + EPS);
        float sh = b1[o] - m1[o] * sc;
        const float* c = &Cs[row * EC_LD + col];
        float4 v;
        v.x = fminf(fmaxf(c[0] * sc + sh, 0.f), 6.f);
        v.y = fminf(fmaxf(c[1] * sc + sh, 0.f), 6.f);
        v.z = fminf(fmaxf(c[2] * sc + sh, 0.f), 6.f);
        v.w = fminf(fmaxf(c[3] * sc + sh, 0.f), 6.f);
        *(float4*)&g_h1[(b * P0 + o) * HW + nBase + col] = v;
    }
}

// ---------------------------------------------------------------------------
// Kernel 2: FUSED depthwise(3x3) + BN2 + ReLU6 + 1x1 project (384->72)
//           + BN3 + scatter(idx) + residual  ->  out (preserved channels).
//
// Block = (b, 2-row stripe of 112 px). Loops over 12 chunks of 32 expanded
// channels: stage h1 chunk (4 rows x 58 cols halo) in smem, depthwise to
// h2 chunk (tf32, [32][N=128pad]), wmma-accumulate Wp[96x32] x h2[32x128]
// across chunks. Epilogue: BN3 + scatter + residual.
//
// 8 warps as 2(M=96 rows, 48 each) x 4(N=128 cols, 32 each); acc 3x2 frags.
// Dynamic smem: h1s 32*232 + h2s 32*132 + Ws 96*36 = 15104 floats = 60,416 B
// (3 blocks/SM). Epilogue Cs[96][132] reuses the same buffer.
// grid = (28, 32), block = 256
// ---------------------------------------------------------------------------
#define FH1   232            // 4*58 per channel
#define FH2LD 132            // h2 leading dim (128 + pad)
#define FWLD  36             // Ws leading dim (32 + pad)
#define FCLD  132            // Cs leading dim
#define OFF_H2 (32 * FH1)            // 7424
#define OFF_WS (OFF_H2 + 32 * FH2LD) // 11648
#define FSMEM  ((OFF_WS + 96 * FWLD) * 4)  // 60,416 B

__global__ __launch_bounds__(256)
void dwproj_kernel(const float* __restrict__ x,
                   const float* __restrict__ dwW,
                   const float* __restrict__ wp,
                   const float* __restrict__ g2, const float* __restrict__ b2,
                   const float* __restrict__ m2, const float* __restrict__ v2,
                   const float* __restrict__ g3, const float* __restrict__ b3,
                   const float* __restrict__ m3, const float* __restrict__ v3,
                   const int* __restrict__ idx,
                   float* __restrict__ out)
{
    extern __shared__ float sm[];
    float* h1s = sm;             // [32][FH1]   fp32 with halo
    float* h2s = sm + OFF_H2;    // [32][FH2LD] tf32 (cols 112..127 zero)
    float* Ws  = sm + OFF_WS;    // [96][FWLD]  tf32 (rows 72..95 zero)
    float* Cs  = sm;             // epilogue reuse [96][FCLD] (12672 <= 15104)

    const int tid  = threadIdx.x;
    const int wid  = tid >> 5;
    const int lane = tid & 31;
    const int r0   = blockIdx.x * 2;   // first interior row of stripe
    const int b    = blockIdx.y;

    // Zero h2s pad cols 112..127 once (never written by dw).
    for (int t = tid; t < 32 * 16; t += 256) {
        int c = t >> 4, q = 112 + (t & 15);
        h2s[c * FH2LD + q] = 0.f;
    }

    const int wm = (wid & 1) * 48;     // M offset: 0 or 48 (3 tiles of 16)
    const int wn = (wid >> 1) * 32;    // N offset: 0,32,64,96 (2 tiles)

    wmma::fragment<wmma::accumulator, 16, 16, 8, float> acc[3][2];
    #pragma unroll
    for (int i = 0; i < 3; i++)
        #pragma unroll
        for (int j = 0; j < 2; j++) wmma::fill_fragment(acc[i][j], 0.f);

    // dw thread mapping (fixed per thread): channel = tid>>3, px stride 8
    const int dwc = tid >> 3;          // 0..31 within chunk
    const int dwp = tid & 7;

    for (int cc = 0; cc < 12; cc++) {
        const int C0 = cc * 32;
        __syncthreads();   // prior mma done before overwriting h1s/Ws/h2s

        // --- load h1 chunk with halo: warp w -> 16 (ch,row) pairs
        #pragma unroll
        for (int i = 0; i < 16; i++) {
            int pi = wid * 16 + i;       // 0..127
            int ch = pi >> 2, r = pi & 3;
            int y  = r0 - 1 + r;
            float* dst = &h1s[ch * FH1 + r * 58];
            if (y >= 0 && y < HH) {
                const float* src = &g_h1[((size_t)(b * P0 + C0 + ch)) * HW + y * WW];
                #pragma unroll
                for (int qq = 0; qq < 2; qq++) {
                    int q = lane + 32 * qq;
                    if (q < 58) {
                        int xx = q - 1;
                        dst[q] = (xx >= 0 && xx < WW) ? src[xx] : 0.f;
                    }
                }
            } else {
                #pragma unroll
                for (int qq = 0; qq < 2; qq++) {
                    int q = lane + 32 * qq;
                    if (q < 58) dst[q] = 0.f;
                }
            }
        }
        // --- load Wp chunk (rows 72..95 zero)
        for (int t = tid; t < 96 * 32; t += 256) {
            int m = t >> 5, k = t & 31;
            float v = (m < P1) ? wp[m * P0 + C0 + k] : 0.f;
            Ws[m * FWLD + k] = wmma::__float_to_tf32(v);
        }
        __syncthreads();

        // --- depthwise 3x3 + BN2 + ReLU6 -> h2s (tf32)
        {
            int gch = C0 + dwc;
            float w0 = dwW[gch * 9 + 0], w1 = dwW[gch * 9 + 1], w2 = dwW[gch * 9 + 2];
            float w3 = dwW[gch * 9 + 3], w4 = dwW[gch * 9 + 4], w5 = dwW[gch * 9 + 5];
            float w6 = dwW[gch * 9 + 6], w7 = dwW[gch * 9 + 7], w8 = dwW[gch * 9 + 8];
            float sc = g2[gch] * rsqrtf(v2[gch] + EPS);
            float sh = b2[gch] - m2[gch] * sc;
            const float* hc = &h1s[dwc * FH1];
            float* oc = &h2s[dwc * FH2LD];
            #pragma unroll
            for (int p = dwp; p < 112; p += 8) {
                int rr = p / 56, col = p - rr * 56;   // rr in {0,1}
                const float* t0 = hc + rr * 58 + col; // top-left of 3x3 window
                float a = w0 * t0[0]  + w1 * t0[1]  + w2 * t0[2];
                a = fmaf(w3, t0[58], fmaf(w4, t0[59], fmaf(w5, t0[60], a)));
                a = fmaf(w6, t0[116], fmaf(w7, t0[117], fmaf(w8, t0[118], a)));
                oc[p] = wmma::__float_to_tf32(fminf(fmaxf(a * sc + sh, 0.f), 6.f));
            }
        }
        __syncthreads();

        // --- project GEMM accumulate: [96x32] x [32x128]
        #pragma unroll
        for (int ks = 0; ks < 32; ks += 8) {
            wmma::fragment<wmma::matrix_a, 16, 16, 8, wmma::precision::tf32, wmma::row_major> af[3];
            wmma::fragment<wmma::matrix_b, 16, 16, 8, wmma::precision::tf32, wmma::row_major> bf[2];
            #pragma unroll
            for (int i = 0; i < 3; i++)
                wmma::load_matrix_sync(af[i], &Ws[(wm + i * 16) * FWLD + ks], FWLD);
            #pragma unroll
            for (int j = 0; j < 2; j++)
                wmma::load_matrix_sync(bf[j], &h2s[ks * FH2LD + wn + j * 16], FH2LD);
            #pragma unroll
            for (int i = 0; i < 3; i++)
                #pragma unroll
                for (int j = 0; j < 2; j++)
                    wmma::mma_sync(acc[i][j], af[i], bf[j], acc[i][j]);
        }
    }

    __syncthreads();   // all mma done; reuse smem as Cs
    #pragma unroll
    for (int i = 0; i < 3; i++)
        #pragma unroll
        for (int j = 0; j < 2; j++)
            wmma::store_matrix_sync(&Cs[(wm + i * 16) * FCLD + wn + j * 16],
                                    acc[i][j], FCLD, wmma::mem_row_major);
    __syncthreads();

    // --- Epilogue: BN3 + scatter + residual, float4. 72 rows x 28 float4.
    for (int t = tid; t < P1 * 28; t += 256) {
        int o = t / 28, q = t - o * 28;
        int p = q * 4;                       // 0..108
        int rr = p / 56, col = p - rr * 56;
        float sc = g3[o] * rsqrtf(v3[o] + EPS);
        float sh = b3[o] - m3[o] * sc;
        int co = idx[o];
        size_t base = ((size_t)(b * CIN + co)) * HW + (r0 + rr) * WW + col;
        float4 xv = *(const float4*)&x[base];
        const float* c = &Cs[o * FCLD + p];
        float4 v;
        v.x = xv.x + (c[0] * sc + sh);
        v.y = xv.y + (c[1] * sc + sh);
        v.z = xv.z + (c[2] * sc + sh);
        v.w = xv.w + (c[3] * sc + sh);
        *(float4*)&out[base] = v;
    }
}

// ---------------------------------------------------------------------------
extern "C" void kernel_launch(void* const* d_in, const int* in_sizes, int n_in,
                              void* d_out, int out_size)
{
    const float* x  = (const float*)d_in[0];
    const float* we = (const float*)d_in[1];
    const float* dw = (const float*)d_in[2];
    const float* wp = (const float*)d_in[3];
    const float* g1 = (const float*)d_in[4];
    const float* b1 = (const float*)d_in[5];
    const float* m1 = (const float*)d_in[6];
    const float* v1 = (const float*)d_in[7];
    const float* g2 = (const float*)d_in[8];
    const float* b2 = (const float*)d_in[9];
    const float* m2 = (const float*)d_in[10];
    const float* v2 = (const float*)d_in[11];
    const float* g3 = (const float*)d_in[12];
    const float* b3 = (const float*)d_in[13];
    const float* m3 = (const float*)d_in[14];
    const float* v3 = (const float*)d_in[15];
    const int*   idx = (const int*)d_in[16];
    float* out = (float*)d_out;

    // Residual identity; preserved channels overwritten by dwproj_kernel.
    cudaMemcpyAsync(out, x, (size_t)B_ * CIN * HW * sizeof(float),
                    cudaMemcpyDeviceToDevice, 0);

    {
        const int smem = (128 * EA_LD + 96 * EB_LD) * sizeof(float);  // 77,312
        cudaFuncSetAttribute(expand_kernel,
                             cudaFuncAttributeMaxDynamicSharedMemorySize, smem);
        dim3 grid(HW / 64, P0 / 128, B_);   // (49, 3, 32)
        expand_kernel<<<grid, 256, smem>>>(x, we, g1, b1, m1, v1);
    }
    {
        cudaFuncSetAttribute(dwproj_kernel,
                             cudaFuncAttributeMaxDynamicSharedMemorySize, FSMEM);
        dim3 grid(HH / 2, B_);              // (28, 32)
        dwproj_kernel<<<grid, 256, FSMEM>>>(x, dw, wp,
                                            g2, b2, m2, v2,
                                            g3, b3, m3, v3, idx, out);
    }
}